// round 4
// baseline (speedup 1.0000x reference)
#include <cuda_runtime.h>

#define BH 32
#define L 2048
#define D 64
#define TQ 32
#define SROW 68            // smem row stride in floats (odd float4 count -> conflict-free strided cols)
#define TK1 128
#define NT1 (L / TK1)      // 16
#define TK2 64
#define NT2 (L / TK2)      // 32
#define WIN 2

typedef unsigned long long ull;

__device__ __forceinline__ void fma2(ull& d, ull a, ull b) {
    asm("fma.rn.f32x2 %0, %1, %2, %3;" : "=l"(d) : "l"(a), "l"(b), "l"(d));
}
__device__ __forceinline__ float lohi(ull a) {
    float lo, hi; asm("mov.b64 {%0,%1}, %2;" : "=f"(lo), "=f"(hi) : "l"(a));
    return lo + hi;
}

// scratch (module-static, no runtime allocation)
__device__ int g_perm[BH][L];
__device__ int g_ng[BH];
__device__ float g_out_scr[(size_t)BH * L * D];
__device__ float g_attn_scr[(size_t)BH * L * L];

// ---------------------------------------------------------------------------
// Kernel 1: gate + compaction.  gate = sigmoid(q.w + b) > 0.5  <=>  q.w + b > 0
// ---------------------------------------------------------------------------
__global__ void gate_kernel(const float* __restrict__ q,
                            const float* __restrict__ gw,
                            const float* __restrict__ gb) {
    __shared__ float4 w_s[16];
    __shared__ int cg, cw;
    int bh = blockIdx.x, t = threadIdx.x;
    if (t < 16) w_s[t] = ((const float4*)gw)[t];
    if (t == 0) { cg = 0; cw = 0; }
    __syncthreads();
    float b = gb[0];
    for (int r = t; r < L; r += 256) {
        const float4* qr = (const float4*)(q + ((size_t)bh * L + r) * D);
        float s = b;
#pragma unroll
        for (int c = 0; c < 16; c++) {
            float4 a = qr[c], w = w_s[c];
            s += a.x * w.x + a.y * w.y + a.z * w.z + a.w * w.w;
        }
        if (s > 0.f) g_perm[bh][atomicAdd(&cg, 1)] = r;
        else         g_perm[bh][L - 1 - atomicAdd(&cw, 1)] = r;
    }
    __syncthreads();
    if (t == 0) g_ng[bh] = cg;
}

// ---------------------------------------------------------------------------
// Kernel 2: gated rows -> dense attention (no mask), exact fp32.
// Padded slots (slot >= ng) run the full uniform code path but NEVER write
// gmem (raw scores, probs, out) — eliminates the duplicate-row write race.
// ---------------------------------------------------------------------------
__global__ void __launch_bounds__(256)
attn_gated(const float* __restrict__ q, const float* __restrict__ k,
           const float* __restrict__ v,
           float* attnp, float* outp) {
    __shared__ __align__(16) float q_s[TQ][SROW];
    __shared__ __align__(16) float kv_s[TK1][SROW];
    __shared__ float rmax_s[TQ], rinv_s[TQ];
    __shared__ int rows_s[TQ];

    float* attn = attnp ? attnp : g_attn_scr;
    float* out  = outp  ? outp  : g_out_scr;

    const int bh = blockIdx.y;
    const int ng = g_ng[bh];
    const int base = (int)blockIdx.x * TQ;
    if (base >= ng) return;
    const int t = threadIdx.x;
    const int w = t >> 5, j = t & 31;
    const int r0 = w * 4;

    if (t < TQ) {
        int slot = base + t;
        rows_s[t] = g_perm[bh][slot < ng ? slot : ng - 1];
    }
    __syncthreads();

    // load Q tile: 32 rows x 16 float4
#pragma unroll
    for (int it = 0; it < 2; it++) {
        int idx = t + it * 256;
        int r = idx >> 4, c4 = idx & 15;
        float4 val = ((const float4*)(q + ((size_t)bh * L + rows_s[r]) * D))[c4];
        *(float4*)&q_s[r][c4 * 4] = val;
    }

    bool vrow[4];
    float* arow[4];
#pragma unroll
    for (int r = 0; r < 4; r++) {
        vrow[r] = (base + r0 + r) < ng;
        arow[r] = attn + ((size_t)bh * L + rows_s[r0 + r]) * (size_t)L;
    }

    float m[4], ssum[4];
#pragma unroll
    for (int r = 0; r < 4; r++) { m[r] = -3.0e38f; ssum[r] = 0.f; }

    // ------------------------- Pass 1 -------------------------
    for (int kt = 0; kt < NT1; kt++) {
        __syncthreads();
#pragma unroll
        for (int it = 0; it < 8; it++) {
            int idx = t + it * 256;  // 2048 float4
            int r = idx >> 4, c4 = idx & 15;
            float4 val = ((const float4*)(k + ((size_t)bh * L + kt * TK1 + r) * D))[c4];
            *(float4*)&kv_s[r][c4 * 4] = val;
        }
        __syncthreads();

        ull acc[4][4];
#pragma unroll
        for (int r = 0; r < 4; r++)
#pragma unroll
            for (int c = 0; c < 4; c++) acc[r][c] = 0ull;

#pragma unroll
        for (int d4 = 0; d4 < 16; d4++) {
            ulonglong2 qv[4], kv[4];
#pragma unroll
            for (int r = 0; r < 4; r++) qv[r] = ((const ulonglong2*)q_s[r0 + r])[d4];
#pragma unroll
            for (int c = 0; c < 4; c++) kv[c] = ((const ulonglong2*)kv_s[j + 32 * c])[d4];
#pragma unroll
            for (int r = 0; r < 4; r++)
#pragma unroll
                for (int c = 0; c < 4; c++) {
                    fma2(acc[r][c], qv[r].x, kv[c].x);
                    fma2(acc[r][c], qv[r].y, kv[c].y);
                }
        }

        float s[4][4];
#pragma unroll
        for (int r = 0; r < 4; r++)
#pragma unroll
            for (int c = 0; c < 4; c++) s[r][c] = lohi(acc[r][c]) * 0.125f;

#pragma unroll
        for (int r = 0; r < 4; r++) {
            float tm = fmaxf(fmaxf(s[r][0], s[r][1]), fmaxf(s[r][2], s[r][3]));
#pragma unroll
            for (int o = 16; o > 0; o >>= 1) tm = fmaxf(tm, __shfl_xor_sync(0xffffffffu, tm, o));
            float mn = fmaxf(m[r], tm);
            float part = __expf(s[r][0] - mn) + __expf(s[r][1] - mn) +
                         __expf(s[r][2] - mn) + __expf(s[r][3] - mn);
#pragma unroll
            for (int o = 16; o > 0; o >>= 1) part += __shfl_xor_sync(0xffffffffu, part, o);
            ssum[r] = ssum[r] * __expf(m[r] - mn) + part;
            m[r] = mn;
            if (vrow[r]) {
#pragma unroll
                for (int c = 0; c < 4; c++) arow[r][kt * TK1 + j + 32 * c] = s[r][c];
            }
        }
    }

    if (j == 0) {
#pragma unroll
        for (int r = 0; r < 4; r++) {
            rmax_s[r0 + r] = m[r];
            rinv_s[r0 + r] = 1.0f / ssum[r];
        }
    }

    // ------------------------- Pass 2 -------------------------
    float (*p_s)[TK2] = (float(*)[TK2]) & kv_s[64][0];
    float4 oacc[2];
    oacc[0] = make_float4(0.f, 0.f, 0.f, 0.f);
    oacc[1] = make_float4(0.f, 0.f, 0.f, 0.f);
    const int ra = (t >> 4) * 2;   // AV: 2 rows
    const int dg = t & 15;         // AV: 4 dims (float4 index)

    for (int kt = 0; kt < NT2; kt++) {
        __syncthreads();
        // load V tile: 64 rows x 16 float4
#pragma unroll
        for (int it = 0; it < 4; it++) {
            int idx = t + it * 256;
            int r = idx >> 4, c4 = idx & 15;
            float4 val = ((const float4*)(v + ((size_t)bh * L + kt * TK2 + r) * D))[c4];
            *(float4*)&kv_s[r][c4 * 4] = val;
        }
        // normalize scores: p to gmem (valid rows only) + p_s
#pragma unroll
        for (int r = 0; r < 4; r++) {
            float mm = rmax_s[r0 + r], ri = rinv_s[r0 + r];
#pragma unroll
            for (int c = 0; c < 2; c++) {
                int col = j + 32 * c;
                float raw = arow[r][kt * TK2 + col];
                float p = __expf(raw - mm) * ri;
                if (vrow[r]) arow[r][kt * TK2 + col] = p;
                p_s[r0 + r][col] = p;
            }
        }
        __syncthreads();

        // AV accumulate
#pragma unroll 4
        for (int c4 = 0; c4 < 16; c4++) {
            float pa[4], pb[4];
            *(float4*)pa = *(float4*)&p_s[ra][c4 * 4];
            *(float4*)pb = *(float4*)&p_s[ra + 1][c4 * 4];
#pragma unroll
            for (int e = 0; e < 4; e++) {
                float4 vv = *(float4*)&kv_s[c4 * 4 + e][dg * 4];
                oacc[0].x += pa[e] * vv.x; oacc[0].y += pa[e] * vv.y;
                oacc[0].z += pa[e] * vv.z; oacc[0].w += pa[e] * vv.w;
                oacc[1].x += pb[e] * vv.x; oacc[1].y += pb[e] * vv.y;
                oacc[1].z += pb[e] * vv.z; oacc[1].w += pb[e] * vv.w;
            }
        }
    }

#pragma unroll
    for (int rr = 0; rr < 2; rr++)
        if (base + ra + rr < ng)
            ((float4*)(out + ((size_t)bh * L + rows_s[ra + rr]) * D))[dg] = oacc[rr];
}

// ---------------------------------------------------------------------------
// Kernel 3: windowed rows — one warp per row. Exact fp32.
// ---------------------------------------------------------------------------
__global__ void __launch_bounds__(256)
attn_win(const float* __restrict__ q, const float* __restrict__ k,
         const float* __restrict__ v,
         float* attnp, float* outp) {
    float* attn = attnp ? attnp : g_attn_scr;
    float* out  = outp  ? outp  : g_out_scr;

    const int bh = blockIdx.y;
    const int nw = L - g_ng[bh];
    const int widx = blockIdx.x * 8 + (threadIdx.x >> 5);
    if (widx >= nw) return;
    const int lane = threadIdx.x & 31;
    const int i = g_perm[bh][L - 1 - widx];
    const int j0 = max(0, i - WIN), j1 = min(L - 1, i + WIN);
    const int n = j1 - j0 + 1;

    const float* qr = q + ((size_t)bh * L + i) * D;
    float q0 = qr[lane], q1 = qr[lane + 32];

    float p[5];
    float mx = -3.0e38f;
#pragma unroll
    for (int jj = 0; jj < 5; jj++) {
        float sc = -3.0e38f;
        if (jj < n) {
            const float* kr = k + ((size_t)bh * L + j0 + jj) * D;
            float d = q0 * kr[lane] + q1 * kr[lane + 32];
#pragma unroll
            for (int o = 16; o > 0; o >>= 1) d += __shfl_xor_sync(0xffffffffu, d, o);
            sc = d * 0.125f;
        }
        p[jj] = sc;
        mx = fmaxf(mx, sc);
    }
    float sum = 0.f;
#pragma unroll
    for (int jj = 0; jj < 5; jj++) {
        p[jj] = (jj < n) ? __expf(p[jj] - mx) : 0.f;
        sum += p[jj];
    }
    float inv = 1.0f / sum;
#pragma unroll
    for (int jj = 0; jj < 5; jj++) p[jj] *= inv;

    // attn row: zeros except exact window probs
    float4* arow4 = (float4*)(attn + ((size_t)bh * L + i) * (size_t)L);
    const int s_lo = j0 >> 2, s_hi = j1 >> 2;
#pragma unroll
    for (int it = 0; it < 16; it++) {
        int s4 = lane + it * 32;
        if (s4 < s_lo || s4 > s_hi) arow4[s4] = make_float4(0.f, 0.f, 0.f, 0.f);
    }
    if (lane <= s_hi - s_lo) {
        int s4 = s_lo + lane;
        float vv[4];
#pragma unroll
        for (int e = 0; e < 4; e++) {
            int idx = s4 * 4 + e;
            vv[e] = (idx >= j0 && idx <= j1) ? p[idx - j0] : 0.f;
        }
        arow4[s4] = make_float4(vv[0], vv[1], vv[2], vv[3]);
    }

    // out
    float o0 = 0.f, o1 = 0.f;
#pragma unroll
    for (int jj = 0; jj < 5; jj++) {
        if (jj < n) {
            const float* vr = v + ((size_t)bh * L + j0 + jj) * D;
            o0 += p[jj] * vr[lane];
            o1 += p[jj] * vr[lane + 32];
        }
    }
    float* orow = out + ((size_t)bh * L + i) * D;
    orow[lane] = o0;
    orow[lane + 32] = o1;
}

// ---------------------------------------------------------------------------
extern "C" void kernel_launch(void* const* d_in, const int* in_sizes, int n_in,
                              void* d_out, int out_size) {
    const float* q  = (const float*)d_in[0];
    const float* k  = (const float*)d_in[1];
    const float* v  = (const float*)d_in[2];
    const float* gw = (const float*)d_in[3];
    const float* gb = (const float*)d_in[4];

    const long long OUTE = (long long)BH * L * D;        // 4194304
    const long long ATTE = (long long)BH * L * L;        // 134217728

    float* outp = nullptr;
    float* attnp = nullptr;
    if ((long long)out_size == OUTE + ATTE) {
        outp = (float*)d_out;
        attnp = (float*)d_out + OUTE;
    } else if ((long long)out_size == ATTE) {
        attnp = (float*)d_out;          // out -> device scratch
    } else {
        outp = (float*)d_out;           // attn -> device scratch
    }

    gate_kernel<<<BH, 256>>>(q, gw, gb);
    attn_gated<<<dim3(L / TQ, BH), 256>>>(q, k, v, attnp, outp);
    attn_win<<<dim3(L / 8, BH), 256>>>(q, k, v, attnp, outp);
}

// round 5
// speedup vs baseline: 1.0695x; 1.0695x over previous
#include <cuda_runtime.h>

#define BH 32
#define L 2048
#define D 64
#define TQ 64              // query rows per block
#define TK 128             // keys per tile
#define NT (L / TK)        // 16
#define SROW 68            // K/V/Q smem row stride (17 float4, odd -> conflict-free)
#define PSROW 132          // p_s row stride (33 float4, odd)
#define WIN 2

typedef unsigned long long ull;

__device__ __forceinline__ void fma2(ull& d, ull a, ull b) {
    asm("fma.rn.f32x2 %0, %1, %2, %3;" : "=l"(d) : "l"(a), "l"(b), "l"(d));
}
__device__ __forceinline__ void mul2(ull& d, ull a) {
    asm("mul.rn.f32x2 %0, %1, %2;" : "=l"(d) : "l"(d), "l"(a));
}
__device__ __forceinline__ ull pk2(float lo, float hi) {
    ull r; asm("mov.b64 %0, {%1,%2};" : "=l"(r) : "f"(lo), "f"(hi)); return r;
}
__device__ __forceinline__ float lohi(ull a) {
    float lo, hi; asm("mov.b64 {%0,%1}, %2;" : "=f"(lo), "=f"(hi) : "l"(a));
    return lo + hi;
}
__device__ __forceinline__ void unpk(ull a, float& lo, float& hi) {
    asm("mov.b64 {%0,%1}, %2;" : "=f"(lo), "=f"(hi) : "l"(a));
}

// module-static scratch
__device__ int g_perm[BH][L];
__device__ int g_cnt[BH][2];
__device__ float g_out_scr[(size_t)BH * L * D];
__device__ float g_attn_scr[(size_t)BH * L * L];

// ---------------------------------------------------------------------------
// Kernel 0: zero the compaction counters
// ---------------------------------------------------------------------------
__global__ void gate_init() {
    int t = threadIdx.x;
    if (t < BH) { g_cnt[t][0] = 0; g_cnt[t][1] = 0; }
}

// ---------------------------------------------------------------------------
// Kernel 1: gate + compaction, 8 blocks per bh (1 row/thread).
// gate = sigmoid(q.w + b) > 0.5  <=>  q.w + b > 0
// ---------------------------------------------------------------------------
__global__ void __launch_bounds__(256)
gate_kernel(const float* __restrict__ q,
            const float* __restrict__ gw,
            const float* __restrict__ gb) {
    __shared__ float4 w_s[16];
    const int bh = blockIdx.x >> 3, seg = blockIdx.x & 7;
    const int t = threadIdx.x;
    if (t < 16) w_s[t] = ((const float4*)gw)[t];
    __syncthreads();
    const int r = seg * 256 + t;
    const float4* qr = (const float4*)(q + ((size_t)bh * L + r) * D);
    float s = gb[0];
#pragma unroll
    for (int c = 0; c < 16; c++) {
        float4 a = qr[c], w = w_s[c];
        s += a.x * w.x + a.y * w.y + a.z * w.z + a.w * w.w;
    }
    if (s > 0.f) g_perm[bh][atomicAdd(&g_cnt[bh][0], 1)] = r;
    else         g_perm[bh][L - 1 - atomicAdd(&g_cnt[bh][1], 1)] = r;
}

// ---------------------------------------------------------------------------
// Kernel 2: gated rows -> dense attention, fused single pass + in-block renorm.
// Block = 64 permuted query rows, 256 threads (8 warps).
// QK mapping: warp w owns rows w*8..w*8+7; lane j owns cols {j,j+32,j+64,j+96}.
// AV mapping: thread = (rowg = t>>4 -> rows rowg*4..+3) x (dg = t&15 -> dims dg*4..+3).
// Per tile: K->smem, QK (f32x2), stats (shfl), p->p_s, raw s->gmem, f->f_s,
//           rescale oacc, V->smem, AV (f32x2).
// End: out = oacc*inv; renorm sweep over raw scores (exp * inv) in-place.
// ---------------------------------------------------------------------------
__global__ void __launch_bounds__(256)
attn_gated(const float* __restrict__ q, const float* __restrict__ k,
           const float* __restrict__ v,
           float* attnp, float* outp) {
    extern __shared__ float smem[];
    float (*q_s)[SROW]  = (float(*)[SROW])smem;                          // 64 x 68
    float (*kv_s)[SROW] = (float(*)[SROW])(smem + TQ * SROW);            // 128 x 68
    float (*p_s)[PSROW] = (float(*)[PSROW])(smem + TQ * SROW + TK * SROW); // 64 x 132
    float* f_s    = smem + TQ * SROW + TK * SROW + TQ * PSROW;           // 64
    float* rinv_s = f_s + TQ;                                            // 64
    int*   rows_s = (int*)(rinv_s + TQ);                                 // 64

    float* attn = attnp ? attnp : g_attn_scr;
    float* out  = outp  ? outp  : g_out_scr;

    const int bh = blockIdx.y;
    const int ng = g_cnt[bh][0];
    const int base = (int)blockIdx.x * TQ;
    if (base >= ng) return;

    const int t = threadIdx.x;
    const int w = t >> 5, j = t & 31;
    const int qr0 = w * 8;            // QK rows for this warp
    const int rowg = t >> 4;          // AV row group (4 rows)
    const int dg = t & 15;            // AV dim group (float4)

    if (t < TQ) {
        int slot = base + t;
        rows_s[t] = g_perm[bh][slot < ng ? slot : ng - 1];
    }
    __syncthreads();

    // load Q tile: 64 rows x 16 float4
#pragma unroll
    for (int it = 0; it < 4; it++) {
        int idx = t + it * 256;
        int r = idx >> 4, c4 = idx & 15;
        float4 val = ((const float4*)(q + ((size_t)bh * L + rows_s[r]) * D))[c4];
        *(float4*)&q_s[r][c4 * 4] = val;
    }

    float m[8], ssum[8];
#pragma unroll
    for (int r = 0; r < 8; r++) { m[r] = -3.0e38f; ssum[r] = 0.f; }
    ull oacc[4][2];
#pragma unroll
    for (int rr = 0; rr < 4; rr++) { oacc[rr][0] = 0ull; oacc[rr][1] = 0ull; }

    for (int kt = 0; kt < NT; kt++) {
        __syncthreads();    // (a) prev AV done, kv_s free
        // load K tile: 128 rows x 16 float4
#pragma unroll
        for (int it = 0; it < 8; it++) {
            int idx = t + it * 256;
            int r = idx >> 4, c4 = idx & 15;
            float4 val = ((const float4*)(k + ((size_t)bh * L + kt * TK + r) * D))[c4];
            *(float4*)&kv_s[r][c4 * 4] = val;
        }
        __syncthreads();    // (b) K ready

        // ---- QK: 8 rows x 4 cols per thread, f32x2 ----
        ull acc[8][4];
#pragma unroll
        for (int r = 0; r < 8; r++)
#pragma unroll
            for (int c = 0; c < 4; c++) acc[r][c] = 0ull;

#pragma unroll
        for (int d4 = 0; d4 < 16; d4++) {
            ulonglong2 kvv[4];
#pragma unroll
            for (int c = 0; c < 4; c++) kvv[c] = ((const ulonglong2*)kv_s[j + 32 * c])[d4];
#pragma unroll
            for (int r = 0; r < 8; r++) {
                ulonglong2 qq = ((const ulonglong2*)q_s[qr0 + r])[d4];
#pragma unroll
                for (int c = 0; c < 4; c++) {
                    fma2(acc[r][c], qq.x, kvv[c].x);
                    fma2(acc[r][c], qq.y, kvv[c].y);
                }
            }
        }

        // ---- stats + p_s + raw scores ----
        float fexp[8];
#pragma unroll
        for (int r = 0; r < 8; r++) {
            float s0 = lohi(acc[r][0]) * 0.125f;
            float s1 = lohi(acc[r][1]) * 0.125f;
            float s2 = lohi(acc[r][2]) * 0.125f;
            float s3 = lohi(acc[r][3]) * 0.125f;
            float tm = fmaxf(fmaxf(s0, s1), fmaxf(s2, s3));
#pragma unroll
            for (int o = 16; o > 0; o >>= 1) tm = fmaxf(tm, __shfl_xor_sync(0xffffffffu, tm, o));
            float mn = fmaxf(m[r], tm);
            float p0 = __expf(s0 - mn), p1 = __expf(s1 - mn);
            float p2 = __expf(s2 - mn), p3 = __expf(s3 - mn);
            float part = p0 + p1 + p2 + p3;
#pragma unroll
            for (int o = 16; o > 0; o >>= 1) part += __shfl_xor_sync(0xffffffffu, part, o);
            fexp[r] = __expf(m[r] - mn);
            ssum[r] = ssum[r] * fexp[r] + part;
            m[r] = mn;
            float* pr = &p_s[qr0 + r][0];
            pr[j] = p0; pr[j + 32] = p1; pr[j + 64] = p2; pr[j + 96] = p3;
            if (base + qr0 + r < ng) {
                float* ap = attn + ((size_t)bh * L + rows_s[qr0 + r]) * (size_t)L + kt * TK;
                ap[j] = s0; ap[j + 32] = s1; ap[j + 64] = s2; ap[j + 96] = s3;
            }
        }
        if (j == 0) {
#pragma unroll
            for (int r = 0; r < 8; r++) f_s[qr0 + r] = fexp[r];
        }
        __syncthreads();    // (c) p_s/f_s ready; QK reads of kv_s done

        // rescale oacc; load V tile
#pragma unroll
        for (int rr = 0; rr < 4; rr++) {
            float f = f_s[rowg * 4 + rr];
            ull ff = pk2(f, f);
            mul2(oacc[rr][0], ff);
            mul2(oacc[rr][1], ff);
        }
#pragma unroll
        for (int it = 0; it < 8; it++) {
            int idx = t + it * 256;
            int r = idx >> 4, c4 = idx & 15;
            float4 val = ((const float4*)(v + ((size_t)bh * L + kt * TK + r) * D))[c4];
            *(float4*)&kv_s[r][c4 * 4] = val;
        }
        __syncthreads();    // (d) V ready

        // ---- AV: 4 rows x 4 dims per thread, f32x2 ----
#pragma unroll 8
        for (int c4 = 0; c4 < 32; c4++) {
            float4 pa[4];
#pragma unroll
            for (int rr = 0; rr < 4; rr++)
                pa[rr] = *(const float4*)&p_s[rowg * 4 + rr][c4 * 4];
#pragma unroll
            for (int e = 0; e < 4; e++) {
                ulonglong2 vv = ((const ulonglong2*)kv_s[c4 * 4 + e])[dg];
#pragma unroll
                for (int rr = 0; rr < 4; rr++) {
                    float pv = (e == 0) ? pa[rr].x : (e == 1) ? pa[rr].y : (e == 2) ? pa[rr].z : pa[rr].w;
                    ull pp = pk2(pv, pv);
                    fma2(oacc[rr][0], pp, vv.x);
                    fma2(oacc[rr][1], pp, vv.y);
                }
            }
        }
    }

    // per-row final inv for AV writer threads
    if (j == 0) {
#pragma unroll
        for (int r = 0; r < 8; r++) rinv_s[qr0 + r] = 1.0f / ssum[r];
    }
    __syncthreads();

    // ---- out = oacc * inv ----
#pragma unroll
    for (int rr = 0; rr < 4; rr++) {
        int row = rowg * 4 + rr;
        if (base + row < ng) {
            float inv = rinv_s[row];
            float4 o;
            unpk(oacc[rr][0], o.x, o.y);
            unpk(oacc[rr][1], o.z, o.w);
            o.x *= inv; o.y *= inv; o.z *= inv; o.w *= inv;
            ((float4*)(out + ((size_t)bh * L + rows_s[row]) * D))[dg] = o;
        }
    }

    // ---- renorm sweep: raw -> prob, in-place (warp owns its 8 QK rows) ----
#pragma unroll
    for (int r = 0; r < 8; r++) {
        if (base + qr0 + r >= ng) continue;
        float mm = m[r], inv = 1.0f / ssum[r];
        float4* ap = (float4*)(attn + ((size_t)bh * L + rows_s[qr0 + r]) * (size_t)L);
#pragma unroll 4
        for (int c4 = 0; c4 < 16; c4++) {
            int idx = c4 * 32 + j;
            float4 x = ap[idx];
            x.x = __expf(x.x - mm) * inv;
            x.y = __expf(x.y - mm) * inv;
            x.z = __expf(x.z - mm) * inv;
            x.w = __expf(x.w - mm) * inv;
            ap[idx] = x;
        }
    }
}

// ---------------------------------------------------------------------------
// Kernel 3: windowed rows — one warp per row. Exact fp32.
// ---------------------------------------------------------------------------
__global__ void __launch_bounds__(256)
attn_win(const float* __restrict__ q, const float* __restrict__ k,
         const float* __restrict__ v,
         float* attnp, float* outp) {
    float* attn = attnp ? attnp : g_attn_scr;
    float* out  = outp  ? outp  : g_out_scr;

    const int bh = blockIdx.y;
    const int nw = L - g_cnt[bh][0];
    const int widx = blockIdx.x * 8 + (threadIdx.x >> 5);
    if (widx >= nw) return;
    const int lane = threadIdx.x & 31;
    const int i = g_perm[bh][L - 1 - widx];
    const int j0 = max(0, i - WIN), j1 = min(L - 1, i + WIN);
    const int n = j1 - j0 + 1;

    const float* qr = q + ((size_t)bh * L + i) * D;
    float q0 = qr[lane], q1 = qr[lane + 32];

    float p[5];
    float mx = -3.0e38f;
#pragma unroll
    for (int jj = 0; jj < 5; jj++) {
        float sc = -3.0e38f;
        if (jj < n) {
            const float* kr = k + ((size_t)bh * L + j0 + jj) * D;
            float d = q0 * kr[lane] + q1 * kr[lane + 32];
#pragma unroll
            for (int o = 16; o > 0; o >>= 1) d += __shfl_xor_sync(0xffffffffu, d, o);
            sc = d * 0.125f;
        }
        p[jj] = sc;
        mx = fmaxf(mx, sc);
    }
    float sum = 0.f;
#pragma unroll
    for (int jj = 0; jj < 5; jj++) {
        p[jj] = (jj < n) ? __expf(p[jj] - mx) : 0.f;
        sum += p[jj];
    }
    float inv = 1.0f / sum;
#pragma unroll
    for (int jj = 0; jj < 5; jj++) p[jj] *= inv;

    // attn row: zeros except exact window probs
    float4* arow4 = (float4*)(attn + ((size_t)bh * L + i) * (size_t)L);
    const int s_lo = j0 >> 2, s_hi = j1 >> 2;
#pragma unroll
    for (int it = 0; it < 16; it++) {
        int s4 = lane + it * 32;
        if (s4 < s_lo || s4 > s_hi) arow4[s4] = make_float4(0.f, 0.f, 0.f, 0.f);
    }
    if (lane <= s_hi - s_lo) {
        int s4 = s_lo + lane;
        float vv[4];
#pragma unroll
        for (int e = 0; e < 4; e++) {
            int idx = s4 * 4 + e;
            vv[e] = (idx >= j0 && idx <= j1) ? p[idx - j0] : 0.f;
        }
        arow4[s4] = make_float4(vv[0], vv[1], vv[2], vv[3]);
    }

    // out
    float o0 = 0.f, o1 = 0.f;
#pragma unroll
    for (int jj = 0; jj < 5; jj++) {
        if (jj < n) {
            const float* vr = v + ((size_t)bh * L + j0 + jj) * D;
            o0 += p[jj] * vr[lane];
            o1 += p[jj] * vr[lane + 32];
        }
    }
    float* orow = out + ((size_t)bh * L + i) * D;
    orow[lane] = o0;
    orow[lane + 32] = o1;
}

// ---------------------------------------------------------------------------
extern "C" void kernel_launch(void* const* d_in, const int* in_sizes, int n_in,
                              void* d_out, int out_size) {
    const float* q  = (const float*)d_in[0];
    const float* k  = (const float*)d_in[1];
    const float* v  = (const float*)d_in[2];
    const float* gw = (const float*)d_in[3];
    const float* gb = (const float*)d_in[4];

    const long long OUTE = (long long)BH * L * D;        // 4194304
    const long long ATTE = (long long)BH * L * L;        // 134217728

    float* outp = nullptr;
    float* attnp = nullptr;
    if ((long long)out_size == OUTE + ATTE) {
        outp = (float*)d_out;
        attnp = (float*)d_out + OUTE;
    } else if ((long long)out_size == ATTE) {
        attnp = (float*)d_out;          // out -> device scratch
    } else {
        outp = (float*)d_out;           // attn -> device scratch
    }

    const int SMEMB = (TQ * SROW + TK * SROW + TQ * PSROW + 2 * TQ) * 4 + TQ * 4 + 256;
    // Set once per call; persists across calls (first call is outside capture).
    cudaFuncSetAttribute(attn_gated, cudaFuncAttributeMaxDynamicSharedMemorySize, SMEMB);

    gate_init<<<1, 64>>>();
    gate_kernel<<<BH * 8, 256>>>(q, gw, gb);
    attn_gated<<<dim3(L / TQ, BH), 256, SMEMB>>>(q, k, v, attnp, outp);
    attn_win<<<dim3(L / 8, BH), 256>>>(q, k, v, attnp, outp);
}